// round 3
// baseline (speedup 1.0000x reference)
#include <cuda_runtime.h>

#define NB 16
#define CH 256
#define KS 6
#define MS 22
#define HO 17                      // MS - KS + 1
#define OUT_PER_N (HO*HO)          // 289
#define TOT_OUT (NB*OUT_PER_N)     // 4624
#define CPB 16                     // channels per block
#define NCHUNK (CH/CPB)            // 16
#define RS 25                      // padded smem row stride (conflict-free scalar LDS)
#define CSTR (MS*RS)               // 550 floats per channel tile
#define TPB 544                    // 17 oy * 16 ch * 2 k-halves = 17 warps
#define NSLICE 32                  // 16 ch * 2 halves
#define NBLOCKS (NCHUNK*NB)        // 256
#define VPT 9                      // BN values per thread (544*9 >= 4624)

// scratch (no allocations allowed -> device globals)
__device__ float g_partial[NCHUNK * TOT_OUT];   // [chunk][n*289 + idx]
__device__ int   g_count = 0;                   // always returns to 0 per launch

__device__ __forceinline__ float fsqrt_fast(float a) {
    float r; asm("sqrt.approx.f32 %0, %1;" : "=f"(r) : "f"(a)); return r;
}
__device__ __forceinline__ float ldcg(const float* p) {
    float v; asm volatile("ld.global.cg.f32 %0, [%1];" : "=f"(v) : "l"(p)); return v;
}

// ---------------------------------------------------------------------------
// Single fused kernel:
//   phase 1 (all 256 blocks): per-(n, 16-channel chunk) sliding correlation,
//     split-k1 (two halves of the 6 filter rows per thread) -> 17 warps/block.
//   phase 2 (last block only): chunk reduction + global BatchNorm + output.
// ---------------------------------------------------------------------------
__global__ __launch_bounds__(TPB) void corr_fused(
    const float* __restrict__ z, const float* __restrict__ x,
    const float* __restrict__ w, const float* __restrict__ bw,
    const float* __restrict__ bb, float* __restrict__ out)
{
    __shared__ float sm[9408];       // 37.6 KB: load layout 8800+576, scratch 32*289=9248
    float* xs = sm;                  // [16][22][RS]
    float* zs = sm + CPB * CSTR;     // [16][36]

    const int chunk = blockIdx.x;
    const int n     = blockIdx.y;
    const int t     = threadIdx.x;

    // --- cooperative load with fused sqrt (each HBM element read once) ---
    const float* xg = x + (size_t)(n * CH + chunk * CPB) * (MS * MS);
    for (int e = t; e < CPB * MS * MS; e += TPB) {
        int cl  = e / (MS * MS);
        int rem = e - cl * (MS * MS);
        int r   = rem / MS;
        int col = rem - r * MS;
        xs[cl * CSTR + r * RS + col] = fsqrt_fast(xg[e]);
    }
    const float* zg = z + (size_t)(n * CH + chunk * CPB) * (KS * KS);
    for (int e = t; e < CPB * KS * KS; e += TPB) {
        int cl = e / (KS * KS);
        zs[e] = fsqrt_fast(zg[e]) * w[chunk * CPB + cl];
    }
    __syncthreads();

    // --- compute: thread = (oy, channel lane, k1-half) ---
    const int oy   = t % HO;
    const int cl   = (t / HO) % CPB;
    const int half = t / (HO * CPB);         // 0 or 1
    const float* xb = &xs[cl * CSTR];
    const float* zb = &zs[cl * KS * KS + half * 3 * KS];

    float acc[HO];
#pragma unroll
    for (int i = 0; i < HO; i++) acc[i] = 0.f;

#pragma unroll
    for (int k1 = 0; k1 < 3; k1++) {
        float xr[MS];
#pragma unroll
        for (int j = 0; j < MS; j++) xr[j] = xb[(oy + half * 3 + k1) * RS + j];
#pragma unroll
        for (int k2 = 0; k2 < KS; k2++) {
            float zv = zb[k1 * KS + k2];
#pragma unroll
            for (int ox = 0; ox < HO; ox++)
                acc[ox] = fmaf(xr[ox + k2], zv, acc[ox]);
        }
    }

    // --- block reduction over 32 slices (fixed order -> deterministic) ---
    __syncthreads();
    const int slice = half * CPB + cl;
#pragma unroll
    for (int ox = 0; ox < HO; ox++)
        sm[slice * OUT_PER_N + oy * HO + ox] = acc[ox];
    __syncthreads();

    for (int idx = t; idx < OUT_PER_N; idx += TPB) {
        float s = 0.f;
#pragma unroll
        for (int sl = 0; sl < NSLICE; sl++) s += sm[sl * OUT_PER_N + idx];
        g_partial[chunk * TOT_OUT + n * OUT_PER_N + idx] = s;
    }

    // --- last-block-done: chunk reduce + BatchNorm ---
    __threadfence();
    __syncthreads();
    __shared__ bool amLast;
    if (t == 0) {
        int c = atomicAdd(&g_count, 1);
        amLast = (c == NBLOCKS - 1);
    }
    __syncthreads();
    if (!amLast) return;

    // gather mean_coeff values (16-chunk sum * 1/36), coalesced L2 reads
    float v[VPT];
    float lsum = 0.f;
#pragma unroll
    for (int k = 0; k < VPT; k++) {
        int idx = t + k * TPB;
        float s = 0.f;
        if (idx < TOT_OUT) {
#pragma unroll
            for (int ch = 0; ch < NCHUNK; ch++)
                s += ldcg(&g_partial[ch * TOT_OUT + idx]);
            s *= (1.f / (KS * KS));
        }
        v[k] = s;
        lsum += s;
    }

    // two-pass BN over 4624 values (block tree reduce in sm)
    float* sred = sm;
    __shared__ float s_mu, s_scale;
    sred[t] = lsum; __syncthreads();
    for (int s = 512; s > 0; s >>= 1) {
        if (t < s && t + s < TPB) sred[t] += sred[t + s];
        __syncthreads();
    }
    if (t == 0) s_mu = sred[0] / (float)TOT_OUT;
    __syncthreads();
    const float mu = s_mu;

    float lss = 0.f;
#pragma unroll
    for (int k = 0; k < VPT; k++) {
        int idx = t + k * TPB;
        if (idx < TOT_OUT) { float d = v[k] - mu; lss += d * d; }
    }
    sred[t] = lss; __syncthreads();
    for (int s = 512; s > 0; s >>= 1) {
        if (t < s && t + s < TPB) sred[t] += sred[t + s];
        __syncthreads();
    }
    if (t == 0) s_scale = rsqrtf(sred[0] / (float)TOT_OUT + 1e-5f) * bw[0];
    __syncthreads();
    const float scale = s_scale;
    const float bias  = bb[0];

#pragma unroll
    for (int k = 0; k < VPT; k++) {
        int idx = t + k * TPB;
        if (idx < TOT_OUT) out[idx] = (v[k] - mu) * scale + bias;
    }

    if (t == 0) g_count = 0;   // reset for next graph replay
}

extern "C" void kernel_launch(void* const* d_in, const int* in_sizes, int n_in,
                              void* d_out, int out_size)
{
    // default: dict order z, x, weights, bn_weight, bn_bias
    const float* z  = (const float*)d_in[0];
    const float* x  = (const float*)d_in[1];
    const float* w  = (const float*)d_in[2];
    const float* bw = (const float*)d_in[3];
    const float* bb = (const float*)d_in[4];

    // robust identification by element count (bn_weight/bias both size 1: keep order)
    int first_one = -1;
    for (int i = 0; i < n_in; i++) {
        if (in_sizes[i] == NB * CH * KS * KS)      z = (const float*)d_in[i];
        else if (in_sizes[i] == NB * CH * MS * MS) x = (const float*)d_in[i];
        else if (in_sizes[i] == CH)                w = (const float*)d_in[i];
        else if (in_sizes[i] == 1) {
            if (first_one < 0) { bw = (const float*)d_in[i]; first_one = i; }
            else                 bb = (const float*)d_in[i];
        }
    }

    dim3 grid(NCHUNK, NB);                       // 16 x 16 = 256 blocks
    corr_fused<<<grid, TPB>>>(z, x, w, bw, bb, (float*)d_out);
}